// round 16
// baseline (speedup 1.0000x reference)
#include <cuda_runtime.h>
#include <cuda_bf16.h>
#include <float.h>
#include <stdint.h>

#define DIMS      256
#define KCODES    1024
#define HWSZ      1024
#define BATCH     32
#define NROWS     32768
#define NUMEL     8388608
#define WELEMS    262144     // KCODES*DIMS
#define THRESH    0.125f

// dynamic smem layout for the mma kernel
#define SM_A_HI   0          // [16 chunks][128 rows][16 bf16]  = 64 KB
#define SM_A_LO   65536      //                                 = 64 KB
#define SM_W_HI   131072     // [64 codes][256 bf16], stride 528B = 33792
#define SM_W_LO   164864     //                                   = 33792
#define SM_WSQ    198656     // 1024 floats = 4 KB
#define SM_TOTAL  202752

__device__ __align__(16) __nv_bfloat16 g_whi[WELEMS];
__device__ __align__(16) __nv_bfloat16 g_wlo[WELEMS];
__device__ float g_wsq[KCODES];
__device__ float g_loss;
__device__ int   g_idx[NROWS];
__device__ int   g_flags[NROWS];
__device__ int   g_nflag;

// ---------------------------------------------------------------------------
// K1: W -> bf16 hi/lo split, wsq, zero scalars.
// ---------------------------------------------------------------------------
__global__ void vq_prep_kernel(const float* __restrict__ w) {
    if (blockIdx.x == 0 && threadIdx.x == 0) { g_loss = 0.0f; g_nflag = 0; }
    for (int i = blockIdx.x * blockDim.x + threadIdx.x; i < WELEMS;
         i += gridDim.x * blockDim.x) {
        float v = w[i];
        __nv_bfloat16 h = __float2bfloat16(v);
        g_whi[i] = h;
        g_wlo[i] = __float2bfloat16(v - __bfloat162float(h));
    }
    int warp = threadIdx.x >> 5, lane = threadIdx.x & 31;
    int k = blockIdx.x * 8 + warp;
    if (k >= KCODES) return;
    const float* row = w + (size_t)k * DIMS;
    float s = 0.0f;
    #pragma unroll
    for (int j = 0; j < DIMS / 32; j++) { float v = row[lane + j*32]; s += v*v; }
    #pragma unroll
    for (int off = 16; off > 0; off >>= 1)
        s += __shfl_xor_sync(0xFFFFFFFFu, s, off);
    if (lane == 0) g_wsq[k] = s;
}

// ---------------------------------------------------------------------------
// K2: bf16 HMMA (mma.sync m16n8k16) distance GEMM, 3-term split,
//     per-row argmin + margin flags.  CTA = 128 rows x 1024 codes, 8 warps.
// ---------------------------------------------------------------------------
__device__ __forceinline__ void mma_bf16(float* c, const uint32_t* a,
                                         uint32_t b0, uint32_t b1) {
    asm volatile(
        "mma.sync.aligned.m16n8k16.row.col.f32.bf16.bf16.f32 "
        "{%0,%1,%2,%3}, {%4,%5,%6,%7}, {%8,%9}, {%0,%1,%2,%3};"
        : "+f"(c[0]), "+f"(c[1]), "+f"(c[2]), "+f"(c[3])
        : "r"(a[0]), "r"(a[1]), "r"(a[2]), "r"(a[3]), "r"(b0), "r"(b1));
}

extern __shared__ char smem[];

__global__ void __launch_bounds__(256, 1)
vq_mma_kernel(const float* __restrict__ x) {
    const int tid  = threadIdx.x;
    const int lane = tid & 31;
    const int warp = tid >> 5;             // 0..7, owns rows warp*16..+15
    const int tile = blockIdx.x;           // 0..255
    const int b    = tile >> 3;
    const int hw0  = (tile & 7) * 128;
    const float* xb = x + (size_t)b * DIMS * HWSZ + hw0;

    float* wsq_s = (float*)(smem + SM_WSQ);
    for (int i = tid; i < KCODES; i += 256) wsq_s[i] = g_wsq[i];

    // ---- A phase: x tile (128 rows x 256 d) -> bf16 hi/lo in smem ----
    {
        const int row = tid & 127;
        const int d0  = (tid >> 7) * 128;
        #pragma unroll 4
        for (int dd = 0; dd < 128; dd++) {
            const int d = d0 + dd;
            float v = xb[(size_t)d * HWSZ + row];
            __nv_bfloat16 h = __float2bfloat16(v);
            __nv_bfloat16 l = __float2bfloat16(v - __bfloat162float(h));
            const uint32_t off = (uint32_t)(d >> 4) * 4096 + row * 32 + (d & 15) * 2;
            *(__nv_bfloat16*)(smem + SM_A_HI + off) = h;
            *(__nv_bfloat16*)(smem + SM_A_LO + off) = l;
        }
    }

    // per-thread argmin state: two row slots (r, r+8) within the warp's 16
    float best0 = FLT_MAX, sec0 = FLT_MAX, best1 = FLT_MAX, sec1 = FLT_MAX;
    int   idx0 = 0, idx1 = 0;

    const uint32_t a_base = (uint32_t)(warp * 16 + (lane >> 2)) * 32 + (lane & 3) * 4;
    const uint32_t b_code = (uint32_t)(lane >> 2);  // code within n8 tile
    const uint32_t b_koff = (lane & 3) * 4;

    #pragma unroll 1
    for (int ct = 0; ct < 16; ct++) {        // 16 code tiles of 64
        __syncthreads();                      // protect W buffer
        // load W tile: 64 codes x 256 d, hi+lo (uint4 = 8 bf16)
        {
            const int code0 = ct * 64;
            #pragma unroll
            for (int j = 0; j < 8; j++) {
                const int l = j * 256 + tid;          // 0..2047
                const int code = l >> 5, off = l & 31;
                const uint4 vh = *((const uint4*)(g_whi + (size_t)(code0 + code) * DIMS) + off);
                const uint4 vl = *((const uint4*)(g_wlo + (size_t)(code0 + code) * DIMS) + off);
                *(uint4*)(smem + SM_W_HI + code * 528 + off * 16) = vh;
                *(uint4*)(smem + SM_W_LO + code * 528 + off * 16) = vl;
            }
        }
        __syncthreads();

        float acc[8][4];
        #pragma unroll
        for (int nt = 0; nt < 8; nt++)
            #pragma unroll
            for (int i = 0; i < 4; i++) acc[nt][i] = 0.0f;

        #pragma unroll 2
        for (int kc = 0; kc < 16; kc++) {     // k chunks of 16 d
            uint32_t ah[4], al[4];
            const uint32_t ab = (uint32_t)kc * 4096 + a_base;
            ah[0] = *(const uint32_t*)(smem + SM_A_HI + ab);
            ah[1] = *(const uint32_t*)(smem + SM_A_HI + ab + 256);
            ah[2] = *(const uint32_t*)(smem + SM_A_HI + ab + 16);
            ah[3] = *(const uint32_t*)(smem + SM_A_HI + ab + 272);
            al[0] = *(const uint32_t*)(smem + SM_A_LO + ab);
            al[1] = *(const uint32_t*)(smem + SM_A_LO + ab + 256);
            al[2] = *(const uint32_t*)(smem + SM_A_LO + ab + 16);
            al[3] = *(const uint32_t*)(smem + SM_A_LO + ab + 272);

            #pragma unroll
            for (int nt = 0; nt < 8; nt++) {
                const uint32_t wb = (uint32_t)(nt * 8 + b_code) * 528
                                  + (uint32_t)kc * 32 + b_koff;
                const uint32_t bh0 = *(const uint32_t*)(smem + SM_W_HI + wb);
                const uint32_t bh1 = *(const uint32_t*)(smem + SM_W_HI + wb + 16);
                const uint32_t bl0 = *(const uint32_t*)(smem + SM_W_LO + wb);
                const uint32_t bl1 = *(const uint32_t*)(smem + SM_W_LO + wb + 16);
                mma_bf16(acc[nt], ah, bh0, bh1);   // hi * HI
                mma_bf16(acc[nt], ah, bl0, bl1);   // hi * LO
                mma_bf16(acc[nt], al, bh0, bh1);   // lo * HI
            }
        }

        // epilogue: dist = wsq - 2*dot ; per-thread best/second update
        #pragma unroll
        for (int nt = 0; nt < 8; nt++) {
            const int cb = ct * 64 + nt * 8 + (lane & 3) * 2;
            #pragma unroll
            for (int i = 0; i < 4; i++) {
                const int code = cb + (i & 1);
                const float dist = wsq_s[code] - 2.0f * acc[nt][i];
                if (i < 2) {
                    if (dist < best0) { sec0 = best0; best0 = dist; idx0 = code; }
                    else if (dist < sec0) { sec0 = dist; }
                } else {
                    if (dist < best1) { sec1 = best1; best1 = dist; idx1 = code; }
                    else if (dist < sec1) { sec1 = dist; }
                }
            }
        }
    }

    // ---- merge across the 4 lanes sharing each row (lane&3 group) ----
    #pragma unroll
    for (int off = 1; off <= 2; off <<= 1) {
        float ob = __shfl_xor_sync(0xFFFFFFFFu, best0, off);
        int   oi = __shfl_xor_sync(0xFFFFFFFFu, idx0,  off);
        float os = __shfl_xor_sync(0xFFFFFFFFu, sec0,  off);
        if (ob < best0 || (ob == best0 && oi < idx0)) {
            sec0 = fminf(best0, os); best0 = ob; idx0 = oi;
        } else {
            sec0 = fminf(sec0, ob);
        }
        ob = __shfl_xor_sync(0xFFFFFFFFu, best1, off);
        oi = __shfl_xor_sync(0xFFFFFFFFu, idx1,  off);
        os = __shfl_xor_sync(0xFFFFFFFFu, sec1,  off);
        if (ob < best1 || (ob == best1 && oi < idx1)) {
            sec1 = fminf(best1, os); best1 = ob; idx1 = oi;
        } else {
            sec1 = fminf(sec1, ob);
        }
    }

    if ((lane & 3) == 0) {
        const int r0 = b * HWSZ + hw0 + warp * 16 + (lane >> 2);
        g_idx[r0] = idx0;
        g_idx[r0 + 8] = idx1;
        if (sec0 - best0 < THRESH) g_flags[atomicAdd(&g_nflag, 1)] = r0;
        if (sec1 - best1 < THRESH) g_flags[atomicAdd(&g_nflag, 1)] = r0 + 8;
    }
}

// ---------------------------------------------------------------------------
// K3: exact fp32 re-argmin for flagged rows.  Warp-per-code-slice.
// ---------------------------------------------------------------------------
__global__ void __launch_bounds__(256)
vq_rescue_kernel(const float* __restrict__ x, const float* __restrict__ w) {
    __shared__ float xrow[DIMS];
    __shared__ float wv[8];
    __shared__ int   wi[8];
    const int tid = threadIdx.x, lane = tid & 31, warp = tid >> 5;
    const int nf = g_nflag;
    for (int fi = blockIdx.x; fi < nf; fi += gridDim.x) {
        const int row = g_flags[fi];
        const int b = row >> 10, hw = row & 1023;
        __syncthreads();
        xrow[tid] = x[((size_t)b * DIMS + tid) * HWSZ + hw];
        __syncthreads();
        float bv = FLT_MAX; int bi = 0x7FFFFFFF;
        for (int c = warp; c < KCODES; c += 8) {
            const float* wr = w + (size_t)c * DIMS;
            float dot = 0.0f;
            #pragma unroll
            for (int j = 0; j < 8; j++)
                dot = fmaf(xrow[lane + j * 32], wr[lane + j * 32], dot);
            #pragma unroll
            for (int off = 16; off > 0; off >>= 1)
                dot += __shfl_xor_sync(0xFFFFFFFFu, dot, off);
            float dist = g_wsq[c] - 2.0f * dot;
            if (dist < bv || (dist == bv && c < bi)) { bv = dist; bi = c; }
        }
        if (lane == 0) { wv[warp] = bv; wi[warp] = bi; }
        __syncthreads();
        if (tid == 0) {
            float fb = wv[0]; int fbi = wi[0];
            #pragma unroll
            for (int j = 1; j < 8; j++)
                if (wv[j] < fb || (wv[j] == fb && wi[j] < fbi)) {
                    fb = wv[j]; fbi = wi[j];
                }
            g_idx[row] = fbi;
        }
    }
}

// ---------------------------------------------------------------------------
// K4: gather codebook rows, write NCHW output, accumulate loss.
// ---------------------------------------------------------------------------
__global__ void __launch_bounds__(256)
vq_out_kernel(const float* __restrict__ x, const float* __restrict__ w,
              float* __restrict__ out) {
    __shared__ int sidx[128];
    __shared__ float lred[8];
    const int tid = threadIdx.x;
    const int tile = blockIdx.x;
    const int b = tile >> 3, hw0 = (tile & 7) * 128;
    const float* xb = x + (size_t)b * DIMS * HWSZ + hw0;
    float* outb = out + (size_t)b * DIMS * HWSZ + hw0;

    if (tid < 128) sidx[tid] = g_idx[b * HWSZ + hw0 + tid];
    __syncthreads();

    float lsum = 0.0f;
    #pragma unroll 1
    for (int i = tid; i < 128 * (DIMS / 4); i += 256) {
        int m = i & 127, dc = i >> 7;
        float4 q = *(const float4*)&w[(size_t)sidx[m] * DIMS + dc * 4];
        float qv[4] = {q.x, q.y, q.z, q.w};
        #pragma unroll
        for (int j = 0; j < 4; j++) {
            int d = dc * 4 + j;
            float xv = xb[(size_t)d * HWSZ + m];
            float df = qv[j] - xv;
            lsum = fmaf(df, df, lsum);
            outb[(size_t)d * HWSZ + m] = qv[j];
        }
    }
    #pragma unroll
    for (int off = 16; off > 0; off >>= 1)
        lsum += __shfl_xor_sync(0xFFFFFFFFu, lsum, off);
    if ((tid & 31) == 0) lred[tid >> 5] = lsum;
    __syncthreads();
    if (tid == 0) {
        float s = 0.0f;
        #pragma unroll
        for (int j = 0; j < 8; j++) s += lred[j];
        atomicAdd(&g_loss, s);
    }
}

// ---------------------------------------------------------------------------
// K5: finalize loss scalar (codebook + 0.25*commit = 1.25*mean((q-x)^2)).
// ---------------------------------------------------------------------------
__global__ void vq_finalize_kernel(float* __restrict__ out, int out_size) {
    if (out_size > NUMEL)
        out[NUMEL] = g_loss * (1.25f / (float)NUMEL);
}

// ---------------------------------------------------------------------------
extern "C" void kernel_launch(void* const* d_in, const int* in_sizes, int n_in,
                              void* d_out, int out_size) {
    const float* x = (const float*)d_in[0];   // [32, 256, 32, 32] fp32
    const float* w = (const float*)d_in[1];   // [1024, 256] fp32
    float* out = (float*)d_out;

    cudaFuncSetAttribute(vq_mma_kernel,
                         cudaFuncAttributeMaxDynamicSharedMemorySize,
                         SM_TOTAL);

    vq_prep_kernel<<<128, 256>>>(w);
    vq_mma_kernel<<<256, 256, SM_TOTAL>>>(x);
    vq_rescue_kernel<<<128, 256>>>(x, w);
    vq_out_kernel<<<256, 256>>>(x, w, out);
    vq_finalize_kernel<<<1, 1>>>(out, out_size);
}